// round 15
// baseline (speedup 1.0000x reference)
#include <cuda_runtime.h>
#include <cuda_bf16.h>

#define CLS    1000
#define CLS4   250               // CLS / 4
#define CLS2   500               // CLS / 2 (bf16 pairs)
#define NB     65536             // batch
#define TINV   (1.0f/0.3f)
#define TPS    16                // samples per tile (= consumer warps)
#define NTILES (NB / TPS)        // 4096
#define GRID   148               // persistent: 1 CTA per SM
#define CWARPS 16                // consumer warps
#define NWARPS (CWARPS + 1)      // +1 producer warp
#define THREADS (NWARPS * 32)    // 544
#define STAGES 3
#define STAGE_BYTES (TPS * CLS * 4)   // 64000, multiple of 16
#define SMEM_DYN (STAGES * STAGE_BYTES)  // 192000 B

__device__ __nv_bfloat162 g_soft[CLS * CLS2]; // softmax(-S[c]/T) rows, bf16, 2 MB
__device__ float g_partial[GRID];             // per-CTA loss partials
__device__ unsigned int g_soft_rows = 0;      // completed soft rows (0..1000)
__device__ unsigned int g_count = 0;          // last-block-done counter

__device__ __forceinline__ float bflo(unsigned int r) { return __uint_as_float(r << 16); }
__device__ __forceinline__ float bfhi(unsigned int r) { return __uint_as_float(r & 0xFFFF0000u); }

__device__ __forceinline__ void mbar_wait(unsigned mb, unsigned parity)
{
    unsigned done;
    do {
        asm volatile("{\n\t.reg .pred p;\n\t"
                     "mbarrier.try_wait.parity.acquire.cta.shared::cta.b64 p, [%1], %2, 0x989680;\n\t"
                     "selp.b32 %0, 1, 0, p;\n\t}"
                     : "=r"(done) : "r"(mb), "r"(parity) : "memory");
    } while (!done);
}

// ---------------------------------------------------------------------------
// Warp-local soft row: SOFT[c][:] = softmax(-S[c][:] / T) in bf16.
// Args in [-3.33, 0] => no max subtraction needed. 8 lane-strided float4,
// warp-reduce, bf16x4 stores.
// ---------------------------------------------------------------------------
__device__ void soft_row(const float* __restrict__ S, int c, int lane)
{
    const float4* __restrict__ src = (const float4*)(S + (size_t)c * CLS);
    float4 e[8];
    #pragma unroll
    for (int i = 0; i < 7; i++) {
        float4 x = src[lane + 32 * i];
        e[i].x = __expf(-x.x * TINV);
        e[i].y = __expf(-x.y * TINV);
        e[i].z = __expf(-x.z * TINV);
        e[i].w = __expf(-x.w * TINV);
    }
    if (lane < 26) {
        float4 x = src[lane + 224];
        e[7].x = __expf(-x.x * TINV);
        e[7].y = __expf(-x.y * TINV);
        e[7].z = __expf(-x.z * TINV);
        e[7].w = __expf(-x.w * TINV);
    } else {
        e[7] = make_float4(0.f, 0.f, 0.f, 0.f);
    }
    float s = 0.f;
    #pragma unroll
    for (int i = 0; i < 8; i++) s += (e[i].x + e[i].y) + (e[i].z + e[i].w);
    #pragma unroll
    for (int o = 16; o; o >>= 1) s += __shfl_xor_sync(~0u, s, o);
    const float inv = 1.0f / s;

    uint2* __restrict__ dst = (uint2*)g_soft + (size_t)c * CLS4;
    #pragma unroll
    for (int i = 0; i < 8; i++) {
        if (i == 7 && lane >= 26) break;
        __nv_bfloat162 lo = __floats2bfloat162_rn(e[i].x * inv, e[i].y * inv);
        __nv_bfloat162 hi = __floats2bfloat162_rn(e[i].z * inv, e[i].w * inv);
        uint2 o2;
        o2.x = *(const unsigned int*)&lo;
        o2.y = *(const unsigned int*)&hi;
        dst[lane + 32 * i] = o2;
    }
}

// ---------------------------------------------------------------------------
// Fused persistent kernel, repaired synchronization. 148 CTAs, 17 warps.
// Producer (warp 16) starts its triple-buffered cp.async.bulk stream at
// kernel start — it does NOT participate in the soft phase or any CTA sync
// after the barrier init. Consumer warps (0-15) first compute soft rows
// (warp-local, per-warp fence + counter increment — NO atomic polling), then
// spin on a plain volatile load of g_soft_rows (non-serializing LTS reads,
// unlike R12's atomicAdd spin which serialized 2368 warps at 32 cyc each).
// Mainloop: prefetch bf16 soft row from L2, wait full, fused exp+dot from
// smem, arrive empty. Deterministic final fold; counters self-reset.
// ---------------------------------------------------------------------------
__global__ __launch_bounds__(THREADS, 1) void fused_kernel(
    const float* __restrict__ logits,
    const void*  __restrict__ targets,
    const float* __restrict__ simmat,
    float* __restrict__ out)
{
    extern __shared__ float tile[];               // STAGES * TPS * CLS floats
    __shared__ __align__(8) unsigned long long full_bar[STAGES], empty_bar[STAGES];
    __shared__ float part[CWARPS];
    __shared__ int   s_t64;
    __shared__ bool  isLast;

    const int tid  = threadIdx.x;
    const int wid  = tid >> 5;
    const int lane = tid & 31;
    const int bid  = blockIdx.x;

    const unsigned full0  = (unsigned)__cvta_generic_to_shared(&full_bar[0]);
    const unsigned empty0 = (unsigned)__cvta_generic_to_shared(&empty_bar[0]);
    const unsigned dst0   = (unsigned)__cvta_generic_to_shared(tile);

    if (tid == 0) {
        #pragma unroll
        for (int s = 0; s < STAGES; s++) {
            asm volatile("mbarrier.init.shared::cta.b64 [%0], 1;"  :: "r"(full0  + 8u*s) : "memory");
            asm volatile("mbarrier.init.shared::cta.b64 [%0], %1;" :: "r"(empty0 + 8u*s), "r"(CWARPS) : "memory");
        }
        // dtype sniff: targets < 1000, so int64 => odd 32-bit words all zero
        const int* tp = (const int*)targets;
        int is64 = 1;
        #pragma unroll
        for (int i = 0; i < 32; i++)
            if (tp[2 * i + 1] != 0) { is64 = 0; break; }
        s_t64 = is64;
    }
    __syncthreads();   // barriers + s_t64 visible; ONLY CTA-wide sync in kernel

    if (wid == CWARPS) {
        // ---------------- producer: starts immediately ----------------
        if (lane == 0) {
            int s = 0, ph = 0;
            for (int t = bid; t < NTILES; t += GRID) {
                mbar_wait(empty0 + 8u*s, (unsigned)(ph ^ 1));
                asm volatile("mbarrier.arrive.expect_tx.shared::cta.b64 _, [%0], %1;"
                             :: "r"(full0 + 8u*s), "r"((unsigned)STAGE_BYTES) : "memory");
                const float* src = logits + (size_t)t * (TPS * CLS);
                asm volatile("cp.async.bulk.shared::cluster.global.mbarrier::complete_tx::bytes "
                             "[%0], [%1], %2, [%3];"
                             :: "r"(dst0 + (unsigned)(s * STAGE_BYTES)), "l"(src),
                                "r"((unsigned)STAGE_BYTES), "r"(full0 + 8u*s) : "memory");
                if (++s == STAGES) { s = 0; ph ^= 1; }
            }
        }
    } else {
        // ---------------- consumers ----------------
        const int t64 = s_t64;

        // phase 1: soft rows, one per consumer warp (gwid < 1000), overlapped
        // with the producer's first bulk copies.
        const int gwid = bid * CWARPS + wid;
        if (gwid < CLS) {
            soft_row(simmat, gwid, lane);
            __syncwarp();
            if (lane == 0) {
                __threadfence();                       // release row stores
                atomicAdd(&g_soft_rows, 1u);           // one RMW per row, 1000 total
            }
            __syncwarp();
        }

        // wait for the full table: plain volatile-load spin (non-serializing)
        if (lane == 0) {
            while (*(volatile unsigned int*)&g_soft_rows < (unsigned)CLS)
                __nanosleep(64);
        }
        __syncwarp();
        __threadfence();                               // acquire row stores

        float loss = 0.f;
        int s = 0, ph = 0;
        for (int t = bid; t < NTILES; t += GRID) {
            const int gw = t * TPS + wid;              // sample id

            long long tg;
            if (t64) tg = ((const long long*)targets)[gw];
            else     tg = ((const int*)targets)[gw];
            const uint2* __restrict__ sf = (const uint2*)g_soft + (size_t)tg * CLS4;
            uint2 sr[8];
            #pragma unroll
            for (int i = 0; i < 7; i++) sr[i] = __ldg(&sf[lane + 32 * i]);
            if (lane < 26) sr[7] = __ldg(&sf[lane + 224]);
            else           sr[7] = make_uint2(0u, 0u);

            mbar_wait(full0 + 8u*s, (unsigned)ph);

            const float4* __restrict__ row =
                (const float4*)(tile + s * (TPS * CLS) + wid * CLS);
            float s0 = 0.f, s1 = 0.f, d0 = 0.f, d1 = 0.f;
            #pragma unroll
            for (int i = 0; i < 7; i++) {
                float4 x = row[lane + 32 * i];
                d0 += x.x * bflo(sr[i].x) + x.z * bflo(sr[i].y);
                d1 += x.y * bfhi(sr[i].x) + x.w * bfhi(sr[i].y);
                s0 += __expf(x.x) + __expf(x.z);
                s1 += __expf(x.y) + __expf(x.w);
            }
            if (lane < 26) {
                float4 x = row[lane + 224];
                d0 += x.x * bflo(sr[7].x) + x.z * bflo(sr[7].y);
                d1 += x.y * bfhi(sr[7].x) + x.w * bfhi(sr[7].y);
                s0 += __expf(x.x) + __expf(x.z);
                s1 += __expf(x.y) + __expf(x.w);
            }
            float es = s0 + s1, dot = d0 + d1;
            #pragma unroll
            for (int o = 16; o; o >>= 1) {
                es  += __shfl_xor_sync(~0u, es,  o);
                dot += __shfl_xor_sync(~0u, dot, o);
            }
            if (lane == 0) loss += __logf(es) - dot;

            __syncwarp();
            if (lane == 0)
                asm volatile("mbarrier.arrive.shared::cta.b64 _, [%0];"
                             :: "r"(empty0 + 8u*s) : "memory");
            if (++s == STAGES) { s = 0; ph ^= 1; }
        }
        if (lane == 0) part[wid] = loss;
    }

    __syncthreads();

    if (tid == 0) {
        float acc = 0.f;
        #pragma unroll
        for (int i = 0; i < CWARPS; i++) acc += part[i];
        g_partial[bid] = acc;
        __threadfence();
        unsigned int done = atomicAdd(&g_count, 1u);
        isLast = (done == (unsigned int)(GRID - 1));
    }
    __syncthreads();

    if (isLast && wid == 0) {
        // 32 lanes fold 148 partials, fixed order: deterministic.
        float acc = 0.f;
        for (int i = lane; i < GRID; i += 32) acc += g_partial[i];
        #pragma unroll
        for (int o = 16; o; o >>= 1) acc += __shfl_xor_sync(~0u, acc, o);
        if (lane == 0) {
            out[0] = acc * (1.0f / (float)NB);
            g_count = 0;                       // self-reset for next graph replay
            g_soft_rows = 0;
        }
    }
}

extern "C" void kernel_launch(void* const* d_in, const int* in_sizes, int n_in,
                              void* d_out, int out_size)
{
    const float* logits  = (const float*)d_in[0];
    const void*  targets = d_in[1];
    const float* simmat  = (const float*)d_in[2];
    float* out = (float*)d_out;

    cudaFuncSetAttribute(fused_kernel, cudaFuncAttributeMaxDynamicSharedMemorySize,
                         SMEM_DYN);

    fused_kernel<<<GRID, THREADS, SMEM_DYN>>>(logits, targets, simmat, out);
}

// round 17
// speedup vs baseline: 2.0929x; 2.0929x over previous
#include <cuda_runtime.h>
#include <cuda_bf16.h>

#define CLS    1000
#define CLS4   250               // CLS / 4
#define CLS2   500               // CLS / 2 (bf16 pairs)
#define NB     65536             // batch
#define TINV   (1.0f/0.3f)
#define TPS    8                 // samples per tile (= consumer warps)
#define NTILES (NB / TPS)        // 8192
#define GRID   296               // persistent: 2 CTAs per SM
#define CWARPS 8                 // consumer warps
#define NWARPS (CWARPS + 1)      // +1 producer warp
#define THREADS (NWARPS * 32)    // 288
#define STAGES 3
#define STAGE_BYTES (TPS * CLS * 4)   // 32000, multiple of 16
#define SMEM_DYN (STAGES * STAGE_BYTES)  // 96000 B -> 2 CTAs/SM

__device__ __nv_bfloat162 g_soft[CLS * CLS2]; // softmax(-S[c]/T) rows, bf16, 2 MB
__device__ float g_partial[GRID];             // per-CTA loss partials
__device__ int   g_t64;                       // 1 if targets are int64
__device__ unsigned int g_count = 0;          // last-block-done counter

__device__ __forceinline__ float bflo(unsigned int r) { return __uint_as_float(r << 16); }
__device__ __forceinline__ float bfhi(unsigned int r) { return __uint_as_float(r & 0xFFFF0000u); }

__device__ __forceinline__ void mbar_wait(unsigned mb, unsigned parity)
{
    unsigned done;
    do {
        asm volatile("{\n\t.reg .pred p;\n\t"
                     "mbarrier.try_wait.parity.acquire.cta.shared::cta.b64 p, [%1], %2, 0x989680;\n\t"
                     "selp.b32 %0, 1, 0, p;\n\t}"
                     : "=r"(done) : "r"(mb), "r"(parity) : "memory");
    } while (!done);
}

// ---------------------------------------------------------------------------
// SOFT[c][:] = softmax(-S[c][:] / T), bf16. Single-phase (args in [-3.33,0]).
// Block 0 / thread 0 sniffs targets dtype (values < 1000 => int64 has all odd
// 32-bit words zero; false-positive prob with int32 data is (1/1000)^32).
// (Identical to the R10 version that measured ~3.5us including launch.)
// ---------------------------------------------------------------------------
__global__ __launch_bounds__(256) void soft_kernel(const float* __restrict__ S,
                                                   const int* __restrict__ tprobe)
{
    __shared__ float red[8];
    __shared__ float s_inv;
    const int c   = blockIdx.x;
    const int tid = threadIdx.x;

    if (c == 0 && tid == 0) {
        int is64 = 1;
        #pragma unroll
        for (int i = 0; i < 32; i++)
            if (tprobe[2 * i + 1] != 0) { is64 = 0; break; }
        g_t64 = is64;
    }

    const float4* __restrict__ src = (const float4*)(S + (size_t)c * CLS);
    const bool active = tid < CLS4;

    float e0 = 0.f, e1 = 0.f, e2 = 0.f, e3 = 0.f;
    if (active) {
        float4 x = src[tid];
        e0 = __expf(-x.x * TINV);
        e1 = __expf(-x.y * TINV);
        e2 = __expf(-x.z * TINV);
        e3 = __expf(-x.w * TINV);
    }
    float s = (e0 + e1) + (e2 + e3);
    #pragma unroll
    for (int o = 16; o; o >>= 1) s += __shfl_xor_sync(~0u, s, o);
    if ((tid & 31) == 0) red[tid >> 5] = s;
    __syncthreads();
    if (tid == 0) {
        float tot = 0.f;
        #pragma unroll
        for (int i = 0; i < 8; i++) tot += red[i];
        s_inv = 1.0f / tot;
    }
    __syncthreads();

    if (active) {
        const float inv = s_inv;
        uint2 o;
        __nv_bfloat162 lo = __floats2bfloat162_rn(e0 * inv, e1 * inv);
        __nv_bfloat162 hi = __floats2bfloat162_rn(e2 * inv, e3 * inv);
        o.x = *(const unsigned int*)&lo;
        o.y = *(const unsigned int*)&hi;
        ((uint2*)g_soft)[(size_t)c * CLS4 + tid] = o;
    }
}

// ---------------------------------------------------------------------------
// Persistent warp-specialized pipeline — R10 structure, 2 CTAs/SM variant.
// 296 CTAs, 9 warps each. Warp 8 (producer, lane 0): triple-buffered
// cp.async.bulk of 32 KB tiles — up to 2 copies in flight per CTA, ~4 per SM,
// two independent producer warps per SM (R10 had one 64 KB copy in flight).
// Warps 0-7 (consumers): sample w of each tile; prefetch bf16 soft row from
// L2 during the copy, then fused exp+dot from smem (conflict-free LDS.128).
// loss_b = log(sum exp x) - dot(soft, x). Deterministic final fold.
// ---------------------------------------------------------------------------
__global__ __launch_bounds__(THREADS, 2) void main_kernel(
    const float* __restrict__ logits,
    const void*  __restrict__ targets,
    float* __restrict__ out)
{
    extern __shared__ float tile[];               // STAGES * TPS * CLS floats
    __shared__ __align__(8) unsigned long long full_bar[STAGES], empty_bar[STAGES];
    __shared__ float part[CWARPS + 1];
    __shared__ bool  isLast;

    const int tid  = threadIdx.x;
    const int wid  = tid >> 5;
    const int lane = tid & 31;
    const int bid  = blockIdx.x;

    const unsigned full0  = (unsigned)__cvta_generic_to_shared(&full_bar[0]);
    const unsigned empty0 = (unsigned)__cvta_generic_to_shared(&empty_bar[0]);
    const unsigned dst0   = (unsigned)__cvta_generic_to_shared(tile);

    if (tid == 0) {
        #pragma unroll
        for (int s = 0; s < STAGES; s++) {
            asm volatile("mbarrier.init.shared::cta.b64 [%0], 1;"  :: "r"(full0  + 8u*s) : "memory");
            asm volatile("mbarrier.init.shared::cta.b64 [%0], %1;" :: "r"(empty0 + 8u*s), "r"(CWARPS) : "memory");
        }
    }
    __syncthreads();

    const int t64 = g_t64;

    if (wid == CWARPS) {
        // ---------------- producer ----------------
        if (lane == 0) {
            int s = 0, ph = 0;
            for (int t = bid; t < NTILES; t += GRID) {
                mbar_wait(empty0 + 8u*s, (unsigned)(ph ^ 1));
                asm volatile("mbarrier.arrive.expect_tx.shared::cta.b64 _, [%0], %1;"
                             :: "r"(full0 + 8u*s), "r"((unsigned)STAGE_BYTES) : "memory");
                const float* src = logits + (size_t)t * (TPS * CLS);
                asm volatile("cp.async.bulk.shared::cluster.global.mbarrier::complete_tx::bytes "
                             "[%0], [%1], %2, [%3];"
                             :: "r"(dst0 + (unsigned)(s * STAGE_BYTES)), "l"(src),
                                "r"((unsigned)STAGE_BYTES), "r"(full0 + 8u*s) : "memory");
                if (++s == STAGES) { s = 0; ph ^= 1; }
            }
        }
        if (lane == 0) part[CWARPS] = 0.f;
    } else {
        // ---------------- consumers ----------------
        float loss = 0.f;
        int s = 0, ph = 0;
        for (int t = bid; t < NTILES; t += GRID) {
            const int gw = t * TPS + wid;          // sample id

            // prefetch target + soft row from L2 (overlaps the bulk copy)
            long long tg;
            if (t64) tg = ((const long long*)targets)[gw];
            else     tg = ((const int*)targets)[gw];
            const uint2* __restrict__ sf = (const uint2*)g_soft + (size_t)tg * CLS4;
            uint2 sr[8];
            #pragma unroll
            for (int i = 0; i < 7; i++) sr[i] = __ldg(&sf[lane + 32 * i]);
            if (lane < 26) sr[7] = __ldg(&sf[lane + 224]);
            else           sr[7] = make_uint2(0u, 0u);

            mbar_wait(full0 + 8u*s, (unsigned)ph);

            const float4* __restrict__ row =
                (const float4*)(tile + s * (TPS * CLS) + wid * CLS);
            float s0 = 0.f, s1 = 0.f, d0 = 0.f, d1 = 0.f;
            #pragma unroll
            for (int i = 0; i < 7; i++) {
                float4 x = row[lane + 32 * i];
                d0 += x.x * bflo(sr[i].x) + x.z * bflo(sr[i].y);
                d1 += x.y * bfhi(sr[i].x) + x.w * bfhi(sr[i].y);
                s0 += __expf(x.x) + __expf(x.z);
                s1 += __expf(x.y) + __expf(x.w);
            }
            if (lane < 26) {
                float4 x = row[lane + 224];
                d0 += x.x * bflo(sr[7].x) + x.z * bflo(sr[7].y);
                d1 += x.y * bfhi(sr[7].x) + x.w * bfhi(sr[7].y);
                s0 += __expf(x.x) + __expf(x.z);
                s1 += __expf(x.y) + __expf(x.w);
            }
            float es = s0 + s1, dot = d0 + d1;
            #pragma unroll
            for (int o = 16; o; o >>= 1) {
                es  += __shfl_xor_sync(~0u, es,  o);
                dot += __shfl_xor_sync(~0u, dot, o);
            }
            if (lane == 0) loss += __logf(es) - dot;

            __syncwarp();
            if (lane == 0)
                asm volatile("mbarrier.arrive.shared::cta.b64 _, [%0];"
                             :: "r"(empty0 + 8u*s) : "memory");
            if (++s == STAGES) { s = 0; ph ^= 1; }
        }
        if (lane == 0) part[wid] = loss;
    }

    __syncthreads();

    if (tid == 0) {
        float acc = 0.f;
        #pragma unroll
        for (int i = 0; i < CWARPS; i++) acc += part[i];
        g_partial[bid] = acc;
        __threadfence();
        unsigned int done = atomicAdd(&g_count, 1u);
        isLast = (done == (unsigned int)(GRID - 1));
    }
    __syncthreads();

    if (isLast && wid == 0) {
        // 32 lanes fold 296 partials, fixed order: deterministic.
        float acc = 0.f;
        for (int i = lane; i < GRID; i += 32) acc += g_partial[i];
        #pragma unroll
        for (int o = 16; o; o >>= 1) acc += __shfl_xor_sync(~0u, acc, o);
        if (lane == 0) {
            out[0] = acc * (1.0f / (float)NB);
            g_count = 0;                      // self-reset for next graph replay
        }
    }
}

extern "C" void kernel_launch(void* const* d_in, const int* in_sizes, int n_in,
                              void* d_out, int out_size)
{
    const float* logits  = (const float*)d_in[0];
    const void*  targets = d_in[1];
    const float* simmat  = (const float*)d_in[2];
    float* out = (float*)d_out;

    cudaFuncSetAttribute(main_kernel, cudaFuncAttributeMaxDynamicSharedMemorySize,
                         SMEM_DYN);

    soft_kernel<<<CLS, 256>>>(simmat, (const int*)targets);
    main_kernel<<<GRID, THREADS, SMEM_DYN>>>(logits, targets, out);
}